// round 15
// baseline (speedup 1.0000x reference)
#include <cuda_runtime.h>
#include <cuda_bf16.h>
#include <mma.h>
using namespace nvcuda;

#define NN 100000
#define NE 3200000
#define NG 512
#define IN_DIM 29
#define HID 128
#define LAT 256

#define SCAN_B 512
#define NBLK ((NN + SCAN_B - 1) / SCAN_B)   // 196
#define TN 64                                // GEMM node tile

// ---------------- scratch (device globals; no allocation allowed) -------------
__device__ float g_dis[NN];
__device__ int   g_indeg[NN];
__device__ int   g_rowptr[NN + 1];
__device__ int   g_fill[NN];
__device__ uint2 g_cw[NE];      // CSR: packed {src, dis[src]*dis[dst]} per edge
__device__ int   g_bsum[NBLK];

__device__ float g_ax[NN * 32];               // aggregated x (29 dims, padded to 32)
__device__ float g_h[NN * HID];               // layer activations (post-relu, fp32)
__device__ float g_hw[NN * HID];              // h @ W  (fp32, self-loop term)
__device__ __nv_bfloat162 g_hwh[NN * 64];     // h @ W  (bf16, neighbor gathers)
__device__ float g_sums[NG * HID];
__device__ float g_cnts[NG];
__device__ float g_pooled[NG * HID];

// ---------------- CSR build ---------------------------------------------------
__global__ void k_zero_deg() {
    int i = blockIdx.x * blockDim.x + threadIdx.x;
    if (i < NN) g_indeg[i] = 0;
}

__global__ void k_count(const int* __restrict__ dst) {
    int e = blockIdx.x * blockDim.x + threadIdx.x;
    if (e < NE) atomicAdd(&g_indeg[dst[e]], 1);
}

__global__ void k_dis() {   // also zeroes fill counters
    int i = blockIdx.x * blockDim.x + threadIdx.x;
    if (i < NN) {
        g_dis[i] = rsqrtf((float)g_indeg[i] + 1.0f);
        g_fill[i] = 0;
    }
}

__global__ void k_scan1() {
    __shared__ int sh[SCAN_B];
    int tid = threadIdx.x;
    int idx = blockIdx.x * SCAN_B + tid;
    int v = (idx < NN) ? g_indeg[idx] : 0;
    sh[tid] = v;
    __syncthreads();
    for (int off = 1; off < SCAN_B; off <<= 1) {
        int t = (tid >= off) ? sh[tid - off] : 0;
        __syncthreads();
        sh[tid] += t;
        __syncthreads();
    }
    if (idx < NN) g_rowptr[idx] = sh[tid] - v;
    if (tid == SCAN_B - 1) g_bsum[blockIdx.x] = sh[tid];
}

// fused: per-block prefix of g_bsum + rowptr fixup
__global__ void k_scan3() {
    __shared__ int red[SCAN_B];
    int tid = threadIdx.x;
    int p = 0;
    for (int i = tid; i < blockIdx.x; i += SCAN_B) p += g_bsum[i];
    red[tid] = p;
    __syncthreads();
    for (int s = SCAN_B / 2; s > 0; s >>= 1) {
        if (tid < s) red[tid] += red[tid + s];
        __syncthreads();
    }
    int offv = red[0];
    int idx = blockIdx.x * SCAN_B + tid;
    if (idx < NN) g_rowptr[idx] += offv;
    if (idx == 0) g_rowptr[NN] = NE;
}

__global__ void k_fill(const int* __restrict__ src, const int* __restrict__ dst) {
    int e = blockIdx.x * blockDim.x + threadIdx.x;
    if (e >= NE) return;
    int s = src[e];
    int d = dst[e];
    int pos = g_rowptr[d] + atomicAdd(&g_fill[d], 1);
    g_cw[pos] = make_uint2((unsigned)s, __float_as_uint(g_dis[s] * g_dis[d]));
}

// -------- layer-1 pre-aggregation: ax[d] = sum_j w_j*x[col_j] + dis^2*x[d] ----
__global__ void k_gather_x(const float* __restrict__ x) {
    int warp = threadIdx.x >> 5, lane = threadIdx.x & 31;
    int node = blockIdx.x * 8 + warp;
    if (node >= NN) return;
    float dd = g_dis[node];
    dd *= dd;
    float a = (lane < IN_DIM) ? __ldg(x + node * IN_DIM + lane) * dd : 0.0f;

    int beg = g_rowptr[node], end = g_rowptr[node + 1];
    int j = beg;
    for (; j + 3 < end; j += 4) {
        uint2 c0 = __ldg(g_cw + j);
        uint2 c1 = __ldg(g_cw + j + 1);
        uint2 c2 = __ldg(g_cw + j + 2);
        uint2 c3 = __ldg(g_cw + j + 3);
        float x0 = 0.f, x1 = 0.f, x2 = 0.f, x3 = 0.f;
        if (lane < IN_DIM) {
            x0 = __ldg(x + (int)c0.x * IN_DIM + lane);
            x1 = __ldg(x + (int)c1.x * IN_DIM + lane);
            x2 = __ldg(x + (int)c2.x * IN_DIM + lane);
            x3 = __ldg(x + (int)c3.x * IN_DIM + lane);
        }
        a += __uint_as_float(c0.y) * x0 + __uint_as_float(c1.y) * x1
           + __uint_as_float(c2.y) * x2 + __uint_as_float(c3.y) * x3;
    }
    for (; j < end; j++) {
        uint2 c = __ldg(g_cw + j);
        if (lane < IN_DIM)
            a += __uint_as_float(c.y) * __ldg(x + (int)c.x * IN_DIM + lane);
    }
    g_ax[node * 32 + lane] = a;
}

// -------- layer-1 GEMM (fused bias+relu): h = relu(ax @ W1 + b1) --------------
__global__ void k_gemm_in_t(const float* __restrict__ W, const float* __restrict__ b) {
    __shared__ float Hs[32][TN];
    int base = blockIdx.x * TN;
    int t = threadIdx.x;
    for (int id = t; id < TN * 8; id += 256) {   // 512 float4
        int n = id >> 3;
        int q = id & 7;
        int node = base + n;
        float4 v = (node < NN) ? ((const float4*)g_ax)[node * 8 + q]
                               : make_float4(0.f, 0.f, 0.f, 0.f);
        Hs[q * 4 + 0][n] = v.x;
        Hs[q * 4 + 1][n] = v.y;
        Hs[q * 4 + 2][n] = v.z;
        Hs[q * 4 + 3][n] = v.w;
    }
    __syncthreads();

    int cg = t & 31;
    int ng = t >> 5;
    float4 acc[8] = {};
    const float4* W4 = (const float4*)W;
    #pragma unroll
    for (int k = 0; k < IN_DIM; k++) {
        float4 w = __ldg(W4 + k * 32 + cg);
        float hk[8];
        *(float4*)&hk[0] = *(const float4*)&Hs[k][ng * 8];
        *(float4*)&hk[4] = *(const float4*)&Hs[k][ng * 8 + 4];
        #pragma unroll
        for (int i = 0; i < 8; i++) {
            acc[i].x += hk[i] * w.x;
            acc[i].y += hk[i] * w.y;
            acc[i].z += hk[i] * w.z;
            acc[i].w += hk[i] * w.w;
        }
    }
    float4 bb = __ldg(((const float4*)b) + cg);
    #pragma unroll
    for (int i = 0; i < 8; i++) {
        int node = base + ng * 8 + i;
        if (node < NN) {
            float4 r;
            r.x = fmaxf(acc[i].x + bb.x, 0.0f);
            r.y = fmaxf(acc[i].y + bb.y, 0.0f);
            r.z = fmaxf(acc[i].z + bb.z, 0.0f);
            r.w = fmaxf(acc[i].w + bb.w, 0.0f);
            ((float4*)g_h)[node * 32 + cg] = r;
        }
    }
}

// -------- tf32 HMMA GEMM: g_h[NN,128] @ W[128,128] -> g_hw (fp32) + g_hwh -----
__global__ void k_gemm_hid_tf32(const float* __restrict__ W) {
    __shared__ float S[TN * HID];   // 32 KB: A tile, then reused for C tile
    int base = blockIdx.x * TN;
    int t = threadIdx.x;

    for (int id = t; id < TN * 32; id += 256) {   // 2048 float4
        int n = id >> 5;
        int node = base + n;
        ((float4*)S)[id] = (node < NN) ? ((const float4*)g_h)[node * 32 + (id & 31)]
                                       : make_float4(0.f, 0.f, 0.f, 0.f);
    }
    __syncthreads();

    int warp = t >> 5;
    int mt = warp & 3;             // 16-row m-tile
    int nb = (warp >> 2) * 64;     // n base: 0 or 64
    wmma::fragment<wmma::accumulator, 16, 16, 8, float> c[4];
    #pragma unroll
    for (int i = 0; i < 4; i++) wmma::fill_fragment(c[i], 0.0f);

    #pragma unroll
    for (int k = 0; k < HID; k += 8) {
        wmma::fragment<wmma::matrix_a, 16, 16, 8, wmma::precision::tf32, wmma::row_major> a;
        wmma::load_matrix_sync(a, S + mt * 16 * HID + k, HID);
        #pragma unroll
        for (int e = 0; e < a.num_elements; e++) a.x[e] = wmma::__float_to_tf32(a.x[e]);
        #pragma unroll
        for (int i = 0; i < 4; i++) {
            wmma::fragment<wmma::matrix_b, 16, 16, 8, wmma::precision::tf32, wmma::row_major> bf;
            wmma::load_matrix_sync(bf, W + k * HID + nb + i * 16, HID);
            #pragma unroll
            for (int e = 0; e < bf.num_elements; e++) bf.x[e] = wmma::__float_to_tf32(bf.x[e]);
            wmma::mma_sync(c[i], a, bf, c[i]);
        }
    }
    __syncthreads();   // all A reads done; reuse S for C
    #pragma unroll
    for (int i = 0; i < 4; i++)
        wmma::store_matrix_sync(S + mt * 16 * HID + nb + i * 16, c[i], HID, wmma::mem_row_major);
    __syncthreads();

    for (int id = t; id < TN * 32; id += 256) {
        int n = id >> 5;
        int q = id & 31;
        int node = base + n;
        if (node < NN) {
            float4 v = ((const float4*)S)[id];
            ((float4*)g_hw)[node * 32 + q] = v;
            g_hwh[node * 64 + q * 2 + 0] = __float22bfloat162_rn(make_float2(v.x, v.y));
            g_hwh[node * 64 + q * 2 + 1] = __float22bfloat162_rn(make_float2(v.z, v.w));
        }
    }
}

// ------- fused gather: h[d] = relu( sum_j w_j*hw[col_j] + dis^2*hw[d] + b ) ----
__global__ void k_gather(const float* __restrict__ b) {
    int warp = threadIdx.x >> 5, lane = threadIdx.x & 31;
    int node = blockIdx.x * 8 + warp;
    if (node >= NN) return;

    float dd = g_dis[node];
    dd *= dd;
    float4 self = ((const float4*)g_hw)[node * 32 + lane];
    float4 bb = __ldg(((const float4*)b) + lane);
    float a0 = self.x * dd + bb.x;
    float a1 = self.y * dd + bb.y;
    float a2 = self.z * dd + bb.z;
    float a3 = self.w * dd + bb.w;

    const uint2* hwB = (const uint2*)g_hwh;
    int beg = g_rowptr[node], end = g_rowptr[node + 1];
    int j = beg;
    for (; j + 3 < end; j += 4) {
        uint2 c0 = __ldg(g_cw + j);
        uint2 c1 = __ldg(g_cw + j + 1);
        uint2 c2 = __ldg(g_cw + j + 2);
        uint2 c3 = __ldg(g_cw + j + 3);
        uint2 u0 = hwB[(int)c0.x * 32 + lane];
        uint2 u1 = hwB[(int)c1.x * 32 + lane];
        uint2 u2 = hwB[(int)c2.x * 32 + lane];
        uint2 u3 = hwB[(int)c3.x * 32 + lane];
        float w0 = __uint_as_float(c0.y), w1 = __uint_as_float(c1.y);
        float w2 = __uint_as_float(c2.y), w3 = __uint_as_float(c3.y);
        float2 f;
        f = __bfloat1622float2(*(const __nv_bfloat162*)&u0.x); a0 += w0 * f.x; a1 += w0 * f.y;
        f = __bfloat1622float2(*(const __nv_bfloat162*)&u0.y); a2 += w0 * f.x; a3 += w0 * f.y;
        f = __bfloat1622float2(*(const __nv_bfloat162*)&u1.x); a0 += w1 * f.x; a1 += w1 * f.y;
        f = __bfloat1622float2(*(const __nv_bfloat162*)&u1.y); a2 += w1 * f.x; a3 += w1 * f.y;
        f = __bfloat1622float2(*(const __nv_bfloat162*)&u2.x); a0 += w2 * f.x; a1 += w2 * f.y;
        f = __bfloat1622float2(*(const __nv_bfloat162*)&u2.y); a2 += w2 * f.x; a3 += w2 * f.y;
        f = __bfloat1622float2(*(const __nv_bfloat162*)&u3.x); a0 += w3 * f.x; a1 += w3 * f.y;
        f = __bfloat1622float2(*(const __nv_bfloat162*)&u3.y); a2 += w3 * f.x; a3 += w3 * f.y;
    }
    for (; j < end; j++) {
        uint2 c = __ldg(g_cw + j);
        uint2 u = hwB[(int)c.x * 32 + lane];
        float w = __uint_as_float(c.y);
        float2 f;
        f = __bfloat1622float2(*(const __nv_bfloat162*)&u.x); a0 += w * f.x; a1 += w * f.y;
        f = __bfloat1622float2(*(const __nv_bfloat162*)&u.y); a2 += w * f.x; a3 += w * f.y;
    }

    float4 o;
    o.x = fmaxf(a0, 0.0f);
    o.y = fmaxf(a1, 0.0f);
    o.z = fmaxf(a2, 0.0f);
    o.w = fmaxf(a3, 0.0f);
    ((float4*)g_h)[node * 32 + lane] = o;
}

// ---------------- pooling (batch is sorted: run-length local accumulate) ------
__global__ void k_zero_pool() {
    int i = blockIdx.x * blockDim.x + threadIdx.x;
    if (i < NG * HID) g_sums[i] = 0.0f;
    if (i < NG) g_cnts[i] = 0.0f;
}

__global__ void k_pool(const int* __restrict__ batch) {
    const int CH = 128;
    int base = blockIdx.x * CH;
    int c = threadIdx.x;
    float acc = 0.0f;
    int cur = -1;
    for (int i = 0; i < CH; i++) {
        int node = base + i;
        if (node >= NN) break;
        int g = __ldg(batch + node);
        if (g != cur) {
            if (cur >= 0) atomicAdd(&g_sums[cur * HID + c], acc);
            cur = g; acc = 0.0f;
        }
        acc += g_h[node * HID + c];
    }
    if (cur >= 0) atomicAdd(&g_sums[cur * HID + c], acc);

    if (threadIdx.x == 0) {
        int cur2 = -1; float cnt = 0.0f;
        for (int i = 0; i < CH; i++) {
            int node = base + i;
            if (node >= NN) break;
            int g = __ldg(batch + node);
            if (g != cur2) {
                if (cur2 >= 0) atomicAdd(&g_cnts[cur2], cnt);
                cur2 = g; cnt = 0.0f;
            }
            cnt += 1.0f;
        }
        if (cur2 >= 0) atomicAdd(&g_cnts[cur2], cnt);
    }
}

__global__ void k_pooldiv() {
    int i = blockIdx.x * blockDim.x + threadIdx.x;
    if (i < NG * HID) {
        int g = i >> 7;
        g_pooled[i] = g_sums[i] / fmaxf(g_cnts[g], 1.0f);
    }
}

// ---------------- heads: mu = pooled@Wmu+bmu ; logvar = pooled@Wlv+blv --------
__global__ void k_head(const float* __restrict__ Wmu, const float* __restrict__ bmu,
                       const float* __restrict__ Wlv, const float* __restrict__ blv,
                       float* __restrict__ out) {
    int g = blockIdx.x;
    __shared__ float p[HID];
    for (int i = threadIdx.x; i < HID; i += blockDim.x) p[i] = g_pooled[g * HID + i];
    __syncthreads();
    int c = threadIdx.x;
    float am = __ldg(bmu + c);
    float al = __ldg(blv + c);
    #pragma unroll 8
    for (int k = 0; k < HID; k++) {
        float pv = p[k];
        am += pv * __ldg(Wmu + k * LAT + c);
        al += pv * __ldg(Wlv + k * LAT + c);
    }
    out[g * LAT + c] = am;
    out[NG * LAT + g * LAT + c] = al;
}

// ---------------- launcher ----------------------------------------------------
extern "C" void kernel_launch(void* const* d_in, const int* in_sizes, int n_in,
                              void* d_out, int out_size) {
    const float* x    = (const float*)d_in[0];
    const int*   ei   = (const int*)d_in[1];   // [2, NE] int32
    const int*   bat  = (const int*)d_in[2];   // [NN] int32
    const float* W1   = (const float*)d_in[3];
    const float* b1   = (const float*)d_in[4];
    const float* W2   = (const float*)d_in[5];
    const float* b2   = (const float*)d_in[6];
    const float* W3   = (const float*)d_in[7];
    const float* b3   = (const float*)d_in[8];
    const float* Wmu  = (const float*)d_in[9];
    const float* bmu  = (const float*)d_in[10];
    const float* Wlv  = (const float*)d_in[11];
    const float* blv  = (const float*)d_in[12];
    float* out = (float*)d_out;

    const int* src = ei;
    const int* dst = ei + NE;

    const int T = 256;
    const int node_blocks = (NN + T - 1) / T;
    const int edge_blocks = (NE + T - 1) / T;
    const int warp8_blocks = (NN + 7) / 8;
    const int tile_blocks = (NN + TN - 1) / TN;

    // ---- CSR build ----
    k_zero_deg<<<node_blocks, T>>>();
    k_count<<<edge_blocks, T>>>(dst);
    k_dis<<<node_blocks, T>>>();
    k_scan1<<<NBLK, SCAN_B>>>();
    k_scan3<<<NBLK, SCAN_B>>>();
    k_fill<<<edge_blocks, T>>>(src, dst);

    // ---- layer 1: aggregate x (29-dim) first, then GEMM+bias+relu ----
    k_gather_x<<<warp8_blocks, T>>>(x);
    k_gemm_in_t<<<tile_blocks, T>>>(W1, b1);

    // ---- layer 2 (tf32 HMMA + bf16 gather) ----
    k_gemm_hid_tf32<<<tile_blocks, T>>>(W2);
    k_gather<<<warp8_blocks, T>>>(b2);

    // ---- layer 3 ----
    k_gemm_hid_tf32<<<tile_blocks, T>>>(W3);
    k_gather<<<warp8_blocks, T>>>(b3);

    // ---- pooling ----
    k_zero_pool<<<(NG * HID + T - 1) / T, T>>>();
    k_pool<<<(NN + 127) / 128, HID>>>(bat);
    k_pooldiv<<<(NG * HID + T - 1) / T, T>>>();

    // ---- heads ----
    k_head<<<NG, LAT>>>(Wmu, bmu, Wlv, blv, out);
}

// round 16
// speedup vs baseline: 1.0066x; 1.0066x over previous
#include <cuda_runtime.h>
#include <cuda_bf16.h>
#include <mma.h>
using namespace nvcuda;

#define NN 100000
#define NE 3200000
#define NG 512
#define IN_DIM 29
#define HID 128
#define LAT 256

#define SCAN_B 512
#define NBLK ((NN + SCAN_B - 1) / SCAN_B)   // 196
#define TN 64                                // GEMM node tile

// ---------------- scratch (device globals; no allocation allowed) -------------
__device__ float g_dis[NN];
__device__ int   g_indeg[NN];
__device__ int   g_rowptr[NN + 1];
__device__ int   g_fill[NN];
__device__ uint2 g_cw[NE];      // CSR: packed {src, dis[src]*dis[dst]} per edge
__device__ int   g_bsum[NBLK];

__device__ float g_ax[NN * 32];               // aggregated x (29 dims, padded to 32)
__device__ __nv_bfloat162 g_hb[NN * 64];      // layer activations (bf16, HMMA A)
__device__ float g_h[NN * HID];               // final layer activations (fp32, pool)
__device__ __nv_bfloat162 g_hwh[NN * 64];     // h @ W (bf16: self + neighbor reads)
__device__ __nv_bfloat16 g_Whi[2 * HID * HID];
__device__ __nv_bfloat16 g_Wlo[2 * HID * HID];
__device__ float g_sums[NG * HID];
__device__ float g_cnts[NG];
__device__ float g_pooled[NG * HID];

// ---------------- CSR build ---------------------------------------------------
__global__ void k_zero_deg() {
    int i = blockIdx.x * blockDim.x + threadIdx.x;
    if (i < NN) g_indeg[i] = 0;
}

__global__ void k_count(const int* __restrict__ dst) {
    int e = blockIdx.x * blockDim.x + threadIdx.x;
    if (e < NE) atomicAdd(&g_indeg[dst[e]], 1);
}

// scan level 1 + fused dis/fill init
__global__ void k_scan1() {
    __shared__ int sh[SCAN_B];
    int tid = threadIdx.x;
    int idx = blockIdx.x * SCAN_B + tid;
    int v = (idx < NN) ? g_indeg[idx] : 0;
    if (idx < NN) {
        g_dis[idx] = rsqrtf((float)v + 1.0f);
        g_fill[idx] = 0;
    }
    sh[tid] = v;
    __syncthreads();
    for (int off = 1; off < SCAN_B; off <<= 1) {
        int t = (tid >= off) ? sh[tid - off] : 0;
        __syncthreads();
        sh[tid] += t;
        __syncthreads();
    }
    if (idx < NN) g_rowptr[idx] = sh[tid] - v;
    if (tid == SCAN_B - 1) g_bsum[blockIdx.x] = sh[tid];
}

// fused: per-block prefix of g_bsum + rowptr fixup
__global__ void k_scan3() {
    __shared__ int red[SCAN_B];
    int tid = threadIdx.x;
    int p = 0;
    for (int i = tid; i < blockIdx.x; i += SCAN_B) p += g_bsum[i];
    red[tid] = p;
    __syncthreads();
    for (int s = SCAN_B / 2; s > 0; s >>= 1) {
        if (tid < s) red[tid] += red[tid + s];
        __syncthreads();
    }
    int offv = red[0];
    int idx = blockIdx.x * SCAN_B + tid;
    if (idx < NN) g_rowptr[idx] += offv;
    if (idx == 0) g_rowptr[NN] = NE;
}

__global__ void k_fill(const int* __restrict__ src, const int* __restrict__ dst) {
    int e = blockIdx.x * blockDim.x + threadIdx.x;
    if (e >= NE) return;
    int s = src[e];
    int d = dst[e];
    int pos = g_rowptr[d] + atomicAdd(&g_fill[d], 1);
    g_cw[pos] = make_uint2((unsigned)s, __float_as_uint(g_dis[s] * g_dis[d]));
}

// ---------------- convert W2, W3 to compensated bf16 pair ---------------------
__global__ void k_convW(const float* __restrict__ W2, const float* __restrict__ W3) {
    int i = blockIdx.x * blockDim.x + threadIdx.x;
    if (i < HID * HID) {
        float w = W2[i];
        __nv_bfloat16 hi = __float2bfloat16(w);
        g_Whi[i] = hi;
        g_Wlo[i] = __float2bfloat16(w - __bfloat162float(hi));
        w = W3[i];
        hi = __float2bfloat16(w);
        g_Whi[HID * HID + i] = hi;
        g_Wlo[HID * HID + i] = __float2bfloat16(w - __bfloat162float(hi));
    }
}

// -------- layer-1 pre-aggregation: ax[d] = sum_j w_j*x[col_j] + dis^2*x[d] ----
__global__ void k_gather_x(const float* __restrict__ x) {
    int warp = threadIdx.x >> 5, lane = threadIdx.x & 31;
    int node = blockIdx.x * 8 + warp;
    if (node >= NN) return;
    float dd = g_dis[node];
    dd *= dd;
    float a = (lane < IN_DIM) ? __ldg(x + node * IN_DIM + lane) * dd : 0.0f;

    int beg = g_rowptr[node], end = g_rowptr[node + 1];
    int j = beg;
    for (; j + 3 < end; j += 4) {
        uint2 c0 = __ldg(g_cw + j);
        uint2 c1 = __ldg(g_cw + j + 1);
        uint2 c2 = __ldg(g_cw + j + 2);
        uint2 c3 = __ldg(g_cw + j + 3);
        float x0 = 0.f, x1 = 0.f, x2 = 0.f, x3 = 0.f;
        if (lane < IN_DIM) {
            x0 = __ldg(x + (int)c0.x * IN_DIM + lane);
            x1 = __ldg(x + (int)c1.x * IN_DIM + lane);
            x2 = __ldg(x + (int)c2.x * IN_DIM + lane);
            x3 = __ldg(x + (int)c3.x * IN_DIM + lane);
        }
        a += __uint_as_float(c0.y) * x0 + __uint_as_float(c1.y) * x1
           + __uint_as_float(c2.y) * x2 + __uint_as_float(c3.y) * x3;
    }
    for (; j < end; j++) {
        uint2 c = __ldg(g_cw + j);
        if (lane < IN_DIM)
            a += __uint_as_float(c.y) * __ldg(x + (int)c.x * IN_DIM + lane);
    }
    g_ax[node * 32 + lane] = a;
}

// -------- layer-1 GEMM (fused bias+relu): h1 = relu(ax @ W1 + b1) -> bf16 -----
__global__ void k_gemm_in_t(const float* __restrict__ W, const float* __restrict__ b) {
    __shared__ float Hs[32][TN];
    int base = blockIdx.x * TN;
    int t = threadIdx.x;
    for (int id = t; id < TN * 8; id += 256) {   // 512 float4
        int n = id >> 3;
        int q = id & 7;
        int node = base + n;
        float4 v = (node < NN) ? ((const float4*)g_ax)[node * 8 + q]
                               : make_float4(0.f, 0.f, 0.f, 0.f);
        Hs[q * 4 + 0][n] = v.x;
        Hs[q * 4 + 1][n] = v.y;
        Hs[q * 4 + 2][n] = v.z;
        Hs[q * 4 + 3][n] = v.w;
    }
    __syncthreads();

    int cg = t & 31;
    int ng = t >> 5;
    float4 acc[8] = {};
    const float4* W4 = (const float4*)W;
    #pragma unroll
    for (int k = 0; k < IN_DIM; k++) {
        float4 w = __ldg(W4 + k * 32 + cg);
        float hk[8];
        *(float4*)&hk[0] = *(const float4*)&Hs[k][ng * 8];
        *(float4*)&hk[4] = *(const float4*)&Hs[k][ng * 8 + 4];
        #pragma unroll
        for (int i = 0; i < 8; i++) {
            acc[i].x += hk[i] * w.x;
            acc[i].y += hk[i] * w.y;
            acc[i].z += hk[i] * w.z;
            acc[i].w += hk[i] * w.w;
        }
    }
    float4 bb = __ldg(((const float4*)b) + cg);
    #pragma unroll
    for (int i = 0; i < 8; i++) {
        int node = base + ng * 8 + i;
        if (node < NN) {
            float rx = fmaxf(acc[i].x + bb.x, 0.0f);
            float ry = fmaxf(acc[i].y + bb.y, 0.0f);
            float rz = fmaxf(acc[i].z + bb.z, 0.0f);
            float rw = fmaxf(acc[i].w + bb.w, 0.0f);
            g_hb[node * 64 + cg * 2 + 0] = __float22bfloat162_rn(make_float2(rx, ry));
            g_hb[node * 64 + cg * 2 + 1] = __float22bfloat162_rn(make_float2(rz, rw));
        }
    }
}

// -------- bf16 HMMA GEMM (compensated W): hwh = hb @ (Whi + Wlo)  -------------
__global__ void k_gemm_hid_wmma(int wsel) {
    __shared__ float S[TN * HID];              // 32 KB: bf16 A (16 KB) then C fp32
    __nv_bfloat16* As = (__nv_bfloat16*)S;
    const __nv_bfloat16* Whi = g_Whi + wsel * HID * HID;
    const __nv_bfloat16* Wlo = g_Wlo + wsel * HID * HID;
    int base = blockIdx.x * TN;
    int t = threadIdx.x;

    // load A tile (bf16 rows, 16 uint4 per row)
    const uint4* srcA = (const uint4*)g_hb;
    for (int id = t; id < TN * 16; id += 256) {
        int n = id >> 4;
        int node = base + n;
        uint4 v = (node < NN) ? srcA[node * 16 + (id & 15)] : make_uint4(0u, 0u, 0u, 0u);
        ((uint4*)As)[id] = v;
    }
    __syncthreads();

    int warp = t >> 5;
    int mt = warp & 3;             // m-tile row (16 rows)
    int nb = (warp >> 2) * 64;     // n base: 0 or 64
    wmma::fragment<wmma::accumulator, 16, 16, 16, float> c[4];
    #pragma unroll
    for (int i = 0; i < 4; i++) wmma::fill_fragment(c[i], 0.0f);

    #pragma unroll
    for (int k = 0; k < HID; k += 16) {
        wmma::fragment<wmma::matrix_a, 16, 16, 16, __nv_bfloat16, wmma::row_major> a;
        wmma::load_matrix_sync(a, As + mt * 16 * HID + k, HID);
        #pragma unroll
        for (int i = 0; i < 4; i++) {
            wmma::fragment<wmma::matrix_b, 16, 16, 16, __nv_bfloat16, wmma::row_major> bhi;
            wmma::load_matrix_sync(bhi, Whi + k * HID + nb + i * 16, HID);
            wmma::mma_sync(c[i], a, bhi, c[i]);
            wmma::fragment<wmma::matrix_b, 16, 16, 16, __nv_bfloat16, wmma::row_major> blo;
            wmma::load_matrix_sync(blo, Wlo + k * HID + nb + i * 16, HID);
            wmma::mma_sync(c[i], a, blo, c[i]);
        }
    }
    __syncthreads();   // done reading A; reuse S for C
    #pragma unroll
    for (int i = 0; i < 4; i++)
        wmma::store_matrix_sync(S + mt * 16 * HID + nb + i * 16, c[i], HID, wmma::mem_row_major);
    __syncthreads();

    // epilogue: write bf16 g_hwh only
    for (int id = t; id < TN * 32; id += 256) {
        int n = id >> 5;
        int q = id & 31;
        int node = base + n;
        if (node < NN) {
            float4 v = ((const float4*)S)[id];
            g_hwh[node * 64 + q * 2 + 0] = __float22bfloat162_rn(make_float2(v.x, v.y));
            g_hwh[node * 64 + q * 2 + 1] = __float22bfloat162_rn(make_float2(v.z, v.w));
        }
    }
}

// ------- fused gather: h[d] = relu( sum_j w_j*hwh[col_j] + dis^2*hwh[d] + b ) --
// mode 0: write bf16 g_hb (feeds next HMMA); mode 1: write fp32 g_h (feeds pool)
__global__ void k_gather(const float* __restrict__ b, int mode) {
    int warp = threadIdx.x >> 5, lane = threadIdx.x & 31;
    int node = blockIdx.x * 8 + warp;
    if (node >= NN) return;

    const uint2* hwB = (const uint2*)g_hwh;
    float dd = g_dis[node];
    dd *= dd;
    uint2 su = hwB[node * 32 + lane];
    float2 s0 = __bfloat1622float2(*(const __nv_bfloat162*)&su.x);
    float2 s1 = __bfloat1622float2(*(const __nv_bfloat162*)&su.y);
    float4 bb = __ldg(((const float4*)b) + lane);
    float a0 = s0.x * dd + bb.x;
    float a1 = s0.y * dd + bb.y;
    float a2 = s1.x * dd + bb.z;
    float a3 = s1.y * dd + bb.w;

    int beg = g_rowptr[node], end = g_rowptr[node + 1];
    int j = beg;
    for (; j + 3 < end; j += 4) {
        uint2 c0 = __ldg(g_cw + j);
        uint2 c1 = __ldg(g_cw + j + 1);
        uint2 c2 = __ldg(g_cw + j + 2);
        uint2 c3 = __ldg(g_cw + j + 3);
        uint2 u0 = hwB[(int)c0.x * 32 + lane];
        uint2 u1 = hwB[(int)c1.x * 32 + lane];
        uint2 u2 = hwB[(int)c2.x * 32 + lane];
        uint2 u3 = hwB[(int)c3.x * 32 + lane];
        float w0 = __uint_as_float(c0.y), w1 = __uint_as_float(c1.y);
        float w2 = __uint_as_float(c2.y), w3 = __uint_as_float(c3.y);
        float2 f;
        f = __bfloat1622float2(*(const __nv_bfloat162*)&u0.x); a0 += w0 * f.x; a1 += w0 * f.y;
        f = __bfloat1622float2(*(const __nv_bfloat162*)&u0.y); a2 += w0 * f.x; a3 += w0 * f.y;
        f = __bfloat1622float2(*(const __nv_bfloat162*)&u1.x); a0 += w1 * f.x; a1 += w1 * f.y;
        f = __bfloat1622float2(*(const __nv_bfloat162*)&u1.y); a2 += w1 * f.x; a3 += w1 * f.y;
        f = __bfloat1622float2(*(const __nv_bfloat162*)&u2.x); a0 += w2 * f.x; a1 += w2 * f.y;
        f = __bfloat1622float2(*(const __nv_bfloat162*)&u2.y); a2 += w2 * f.x; a3 += w2 * f.y;
        f = __bfloat1622float2(*(const __nv_bfloat162*)&u3.x); a0 += w3 * f.x; a1 += w3 * f.y;
        f = __bfloat1622float2(*(const __nv_bfloat162*)&u3.y); a2 += w3 * f.x; a3 += w3 * f.y;
    }
    for (; j < end; j++) {
        uint2 c = __ldg(g_cw + j);
        uint2 u = hwB[(int)c.x * 32 + lane];
        float w = __uint_as_float(c.y);
        float2 f;
        f = __bfloat1622float2(*(const __nv_bfloat162*)&u.x); a0 += w * f.x; a1 += w * f.y;
        f = __bfloat1622float2(*(const __nv_bfloat162*)&u.y); a2 += w * f.x; a3 += w * f.y;
    }

    a0 = fmaxf(a0, 0.0f);
    a1 = fmaxf(a1, 0.0f);
    a2 = fmaxf(a2, 0.0f);
    a3 = fmaxf(a3, 0.0f);
    if (mode == 0) {
        g_hb[node * 64 + lane * 2 + 0] = __float22bfloat162_rn(make_float2(a0, a1));
        g_hb[node * 64 + lane * 2 + 1] = __float22bfloat162_rn(make_float2(a2, a3));
    } else {
        ((float4*)g_h)[node * 32 + lane] = make_float4(a0, a1, a2, a3);
    }
}

// ---------------- pooling (batch is sorted: run-length local accumulate) ------
__global__ void k_zero_pool() {
    int i = blockIdx.x * blockDim.x + threadIdx.x;
    if (i < NG * HID) g_sums[i] = 0.0f;
    if (i < NG) g_cnts[i] = 0.0f;
}

__global__ void k_pool(const int* __restrict__ batch) {
    const int CH = 128;
    int base = blockIdx.x * CH;
    int c = threadIdx.x;
    float acc = 0.0f;
    int cur = -1;
    for (int i = 0; i < CH; i++) {
        int node = base + i;
        if (node >= NN) break;
        int g = __ldg(batch + node);
        if (g != cur) {
            if (cur >= 0) atomicAdd(&g_sums[cur * HID + c], acc);
            cur = g; acc = 0.0f;
        }
        acc += g_h[node * HID + c];
    }
    if (cur >= 0) atomicAdd(&g_sums[cur * HID + c], acc);

    if (threadIdx.x == 0) {
        int cur2 = -1; float cnt = 0.0f;
        for (int i = 0; i < CH; i++) {
            int node = base + i;
            if (node >= NN) break;
            int g = __ldg(batch + node);
            if (g != cur2) {
                if (cur2 >= 0) atomicAdd(&g_cnts[cur2], cnt);
                cur2 = g; cnt = 0.0f;
            }
            cnt += 1.0f;
        }
        if (cur2 >= 0) atomicAdd(&g_cnts[cur2], cnt);
    }
}

__global__ void k_pooldiv() {
    int i = blockIdx.x * blockDim.x + threadIdx.x;
    if (i < NG * HID) {
        int g = i >> 7;
        g_pooled[i] = g_sums[i] / fmaxf(g_cnts[g], 1.0f);
    }
}

// ---------------- heads: mu = pooled@Wmu+bmu ; logvar = pooled@Wlv+blv --------
__global__ void k_head(const float* __restrict__ Wmu, const float* __restrict__ bmu,
                       const float* __restrict__ Wlv, const float* __restrict__ blv,
                       float* __restrict__ out) {
    int g = blockIdx.x;
    __shared__ float p[HID];
    for (int i = threadIdx.x; i < HID; i += blockDim.x) p[i] = g_pooled[g * HID + i];
    __syncthreads();
    int c = threadIdx.x;
    float am = __ldg(bmu + c);
    float al = __ldg(blv + c);
    #pragma unroll 8
    for (int k = 0; k < HID; k++) {
        float pv = p[k];
        am += pv * __ldg(Wmu + k * LAT + c);
        al += pv * __ldg(Wlv + k * LAT + c);
    }
    out[g * LAT + c] = am;
    out[NG * LAT + g * LAT + c] = al;
}

// ---------------- launcher ----------------------------------------------------
extern "C" void kernel_launch(void* const* d_in, const int* in_sizes, int n_in,
                              void* d_out, int out_size) {
    const float* x    = (const float*)d_in[0];
    const int*   ei   = (const int*)d_in[1];   // [2, NE] int32
    const int*   bat  = (const int*)d_in[2];   // [NN] int32
    const float* W1   = (const float*)d_in[3];
    const float* b1   = (const float*)d_in[4];
    const float* W2   = (const float*)d_in[5];
    const float* b2   = (const float*)d_in[6];
    const float* W3   = (const float*)d_in[7];
    const float* b3   = (const float*)d_in[8];
    const float* Wmu  = (const float*)d_in[9];
    const float* bmu  = (const float*)d_in[10];
    const float* Wlv  = (const float*)d_in[11];
    const float* blv  = (const float*)d_in[12];
    float* out = (float*)d_out;

    const int* src = ei;
    const int* dst = ei + NE;

    const int T = 256;
    const int node_blocks = (NN + T - 1) / T;
    const int edge_blocks = (NE + T - 1) / T;
    const int warp8_blocks = (NN + 7) / 8;
    const int tile_blocks = (NN + TN - 1) / TN;

    // ---- CSR build ----
    k_zero_deg<<<node_blocks, T>>>();
    k_count<<<edge_blocks, T>>>(dst);
    k_scan1<<<NBLK, SCAN_B>>>();
    k_scan3<<<NBLK, SCAN_B>>>();
    k_fill<<<edge_blocks, T>>>(src, dst);
    k_convW<<<(HID * HID + T - 1) / T, T>>>(W2, W3);

    // ---- layer 1: aggregate x first, then GEMM+bias+relu -> bf16 h1 ----
    k_gather_x<<<warp8_blocks, T>>>(x);
    k_gemm_in_t<<<tile_blocks, T>>>(W1, b1);

    // ---- layer 2 (bf16 HMMA, compensated W) ----
    k_gemm_hid_wmma<<<tile_blocks, T>>>(0);
    k_gather<<<warp8_blocks, T>>>(b2, 0);

    // ---- layer 3 ----
    k_gemm_hid_wmma<<<tile_blocks, T>>>(1);
    k_gather<<<warp8_blocks, T>>>(b3, 1);

    // ---- pooling ----
    k_zero_pool<<<(NG * HID + T - 1) / T, T>>>();
    k_pool<<<(NN + 127) / 128, HID>>>(bat);
    k_pooldiv<<<(NG * HID + T - 1) / T, T>>>();

    // ---- heads ----
    k_head<<<NG, LAT>>>(Wmu, bmu, Wlv, blv, out);
}

// round 17
// speedup vs baseline: 1.0072x; 1.0006x over previous
#include <cuda_runtime.h>
#include <cuda_bf16.h>
#include <mma.h>
using namespace nvcuda;

#define NN 100000
#define NE 3200000
#define NG 512
#define IN_DIM 29
#define HID 128
#define LAT 256

#define SCAN_B 512
#define NBLK ((NN + SCAN_B - 1) / SCAN_B)   // 196
#define TN 64                                // GEMM node tile

// ---------------- scratch (device globals; no allocation allowed) -------------
__device__ float g_dis[NN];
__device__ int   g_indeg[NN];
__device__ int   g_rowptr[NN + 1];
__device__ int   g_fill[NN];
__device__ uint2 g_cw[NE];      // CSR: packed {src, dis[src]*dis[dst]} per edge
__device__ int   g_bsum[NBLK];

__device__ __nv_bfloat162 g_hb[NN * 64];      // layer activations (bf16, HMMA A)
__device__ float g_h[NN * HID];               // final activations (fp32, pooling)
__device__ __nv_bfloat162 g_hwh[NN * 64];     // h @ W (bf16: self + neighbor reads)
__device__ __nv_bfloat16 g_Whi[2 * HID * HID];
__device__ __nv_bfloat16 g_Wlo[2 * HID * HID];
__device__ float g_sums[NG * HID];
__device__ float g_cnts[NG];

// ---------------- CSR build ---------------------------------------------------
__global__ void k_zero_deg() {
    int i = blockIdx.x * blockDim.x + threadIdx.x;
    if (i < NN) g_indeg[i] = 0;
}

__global__ void k_count(const int* __restrict__ dst) {
    int e = blockIdx.x * blockDim.x + threadIdx.x;
    if (e < NE) atomicAdd(&g_indeg[dst[e]], 1);
}

// scan level 1 + fused dis/fill init
__global__ void k_scan1() {
    __shared__ int sh[SCAN_B];
    int tid = threadIdx.x;
    int idx = blockIdx.x * SCAN_B + tid;
    int v = (idx < NN) ? g_indeg[idx] : 0;
    if (idx < NN) {
        g_dis[idx] = rsqrtf((float)v + 1.0f);
        g_fill[idx] = 0;
    }
    sh[tid] = v;
    __syncthreads();
    for (int off = 1; off < SCAN_B; off <<= 1) {
        int t = (tid >= off) ? sh[tid - off] : 0;
        __syncthreads();
        sh[tid] += t;
        __syncthreads();
    }
    if (idx < NN) g_rowptr[idx] = sh[tid] - v;
    if (tid == SCAN_B - 1) g_bsum[blockIdx.x] = sh[tid];
}

// per-block prefix of g_bsum + rowptr fixup
__global__ void k_scan3() {
    __shared__ int red[SCAN_B];
    int tid = threadIdx.x;
    int p = 0;
    for (int i = tid; i < blockIdx.x; i += SCAN_B) p += g_bsum[i];
    red[tid] = p;
    __syncthreads();
    for (int s = SCAN_B / 2; s > 0; s >>= 1) {
        if (tid < s) red[tid] += red[tid + s];
        __syncthreads();
    }
    int offv = red[0];
    int idx = blockIdx.x * SCAN_B + tid;
    if (idx < NN) g_rowptr[idx] += offv;
    if (idx == 0) g_rowptr[NN] = NE;
}

__global__ void k_fill(const int* __restrict__ src, const int* __restrict__ dst) {
    int e = blockIdx.x * blockDim.x + threadIdx.x;
    if (e >= NE) return;
    int s = src[e];
    int d = dst[e];
    int pos = g_rowptr[d] + atomicAdd(&g_fill[d], 1);
    g_cw[pos] = make_uint2((unsigned)s, __float_as_uint(g_dis[s] * g_dis[d]));
}

// ------- convert W2, W3 to compensated bf16 pair + zero pooling buffers -------
__global__ void k_convW(const float* __restrict__ W2, const float* __restrict__ W3) {
    int i = blockIdx.x * blockDim.x + threadIdx.x;
    if (i < HID * HID) {
        float w = W2[i];
        __nv_bfloat16 hi = __float2bfloat16(w);
        g_Whi[i] = hi;
        g_Wlo[i] = __float2bfloat16(w - __bfloat162float(hi));
        w = W3[i];
        hi = __float2bfloat16(w);
        g_Whi[HID * HID + i] = hi;
        g_Wlo[HID * HID + i] = __float2bfloat16(w - __bfloat162float(hi));
    }
    if (i < NG * HID) g_sums[i] = 0.0f;
    if (i < NG) g_cnts[i] = 0.0f;
}

// -------- layer-1 GEMM: x[NN,29] @ W1[29,128] -> bf16 g_hwh -------------------
__global__ void k_gemm_in_t(const float* __restrict__ x, const float* __restrict__ W) {
    __shared__ float Hs[IN_DIM][TN];
    int base = blockIdx.x * TN;
    int t = threadIdx.x;
    for (int id = t; id < TN * IN_DIM; id += 256) {
        int n = id & 63;
        int kk = id >> 6;
        int node = base + n;
        Hs[kk][n] = (node < NN) ? __ldg(x + node * IN_DIM + kk) : 0.0f;
    }
    __syncthreads();

    int cg = t & 31;
    int ng = t >> 5;
    float4 acc[8] = {};
    const float4* W4 = (const float4*)W;
    #pragma unroll
    for (int k = 0; k < IN_DIM; k++) {
        float4 w = __ldg(W4 + k * 32 + cg);
        float hk[8];
        *(float4*)&hk[0] = *(const float4*)&Hs[k][ng * 8];
        *(float4*)&hk[4] = *(const float4*)&Hs[k][ng * 8 + 4];
        #pragma unroll
        for (int i = 0; i < 8; i++) {
            acc[i].x += hk[i] * w.x;
            acc[i].y += hk[i] * w.y;
            acc[i].z += hk[i] * w.z;
            acc[i].w += hk[i] * w.w;
        }
    }
    #pragma unroll
    for (int i = 0; i < 8; i++) {
        int node = base + ng * 8 + i;
        if (node < NN) {
            g_hwh[node * 64 + cg * 2 + 0] = __float22bfloat162_rn(make_float2(acc[i].x, acc[i].y));
            g_hwh[node * 64 + cg * 2 + 1] = __float22bfloat162_rn(make_float2(acc[i].z, acc[i].w));
        }
    }
}

// -------- bf16 HMMA GEMM (compensated W): hwh = hb @ (Whi + Wlo) --------------
__global__ void k_gemm_hid_wmma(int wsel) {
    __shared__ float S[TN * HID];              // 32 KB: bf16 A (16 KB) then C fp32
    __nv_bfloat16* As = (__nv_bfloat16*)S;
    const __nv_bfloat16* Whi = g_Whi + wsel * HID * HID;
    const __nv_bfloat16* Wlo = g_Wlo + wsel * HID * HID;
    int base = blockIdx.x * TN;
    int t = threadIdx.x;

    const uint4* srcA = (const uint4*)g_hb;
    for (int id = t; id < TN * 16; id += 256) {
        int n = id >> 4;
        int node = base + n;
        uint4 v = (node < NN) ? srcA[node * 16 + (id & 15)] : make_uint4(0u, 0u, 0u, 0u);
        ((uint4*)As)[id] = v;
    }
    __syncthreads();

    int warp = t >> 5;
    int mt = warp & 3;
    int nb = (warp >> 2) * 64;
    wmma::fragment<wmma::accumulator, 16, 16, 16, float> c[4];
    #pragma unroll
    for (int i = 0; i < 4; i++) wmma::fill_fragment(c[i], 0.0f);

    #pragma unroll
    for (int k = 0; k < HID; k += 16) {
        wmma::fragment<wmma::matrix_a, 16, 16, 16, __nv_bfloat16, wmma::row_major> a;
        wmma::load_matrix_sync(a, As + mt * 16 * HID + k, HID);
        #pragma unroll
        for (int i = 0; i < 4; i++) {
            wmma::fragment<wmma::matrix_b, 16, 16, 16, __nv_bfloat16, wmma::row_major> bhi;
            wmma::load_matrix_sync(bhi, Whi + k * HID + nb + i * 16, HID);
            wmma::mma_sync(c[i], a, bhi, c[i]);
            wmma::fragment<wmma::matrix_b, 16, 16, 16, __nv_bfloat16, wmma::row_major> blo;
            wmma::load_matrix_sync(blo, Wlo + k * HID + nb + i * 16, HID);
            wmma::mma_sync(c[i], a, blo, c[i]);
        }
    }
    __syncthreads();
    #pragma unroll
    for (int i = 0; i < 4; i++)
        wmma::store_matrix_sync(S + mt * 16 * HID + nb + i * 16, c[i], HID, wmma::mem_row_major);
    __syncthreads();

    for (int id = t; id < TN * 32; id += 256) {
        int n = id >> 5;
        int q = id & 31;
        int node = base + n;
        if (node < NN) {
            float4 v = ((const float4*)S)[id];
            g_hwh[node * 64 + q * 2 + 0] = __float22bfloat162_rn(make_float2(v.x, v.y));
            g_hwh[node * 64 + q * 2 + 1] = __float22bfloat162_rn(make_float2(v.z, v.w));
        }
    }
}

// ------- fused gather: h[d] = relu( sum_j w_j*hwh[col_j] + dis^2*hwh[d] + b ) --
// mode 0: write bf16 g_hb (feeds next HMMA); mode 1: write fp32 g_h (pooling)
__global__ void k_gather(const float* __restrict__ b, int mode) {
    int warp = threadIdx.x >> 5, lane = threadIdx.x & 31;
    int node = blockIdx.x * 8 + warp;
    if (node >= NN) return;

    const uint2* hwB = (const uint2*)g_hwh;
    float dd = g_dis[node];
    dd *= dd;
    uint2 su = hwB[node * 32 + lane];
    float2 s0 = __bfloat1622float2(*(const __nv_bfloat162*)&su.x);
    float2 s1 = __bfloat1622float2(*(const __nv_bfloat162*)&su.y);
    float4 bb = __ldg(((const float4*)b) + lane);
    float a0 = s0.x * dd + bb.x;
    float a1 = s0.y * dd + bb.y;
    float a2 = s1.x * dd + bb.z;
    float a3 = s1.y * dd + bb.w;

    int beg = g_rowptr[node], end = g_rowptr[node + 1];
    int j = beg;
    for (; j + 3 < end; j += 4) {
        uint2 c0 = __ldg(g_cw + j);
        uint2 c1 = __ldg(g_cw + j + 1);
        uint2 c2 = __ldg(g_cw + j + 2);
        uint2 c3 = __ldg(g_cw + j + 3);
        uint2 u0 = hwB[(int)c0.x * 32 + lane];
        uint2 u1 = hwB[(int)c1.x * 32 + lane];
        uint2 u2 = hwB[(int)c2.x * 32 + lane];
        uint2 u3 = hwB[(int)c3.x * 32 + lane];
        float w0 = __uint_as_float(c0.y), w1 = __uint_as_float(c1.y);
        float w2 = __uint_as_float(c2.y), w3 = __uint_as_float(c3.y);
        float2 f;
        f = __bfloat1622float2(*(const __nv_bfloat162*)&u0.x); a0 += w0 * f.x; a1 += w0 * f.y;
        f = __bfloat1622float2(*(const __nv_bfloat162*)&u0.y); a2 += w0 * f.x; a3 += w0 * f.y;
        f = __bfloat1622float2(*(const __nv_bfloat162*)&u1.x); a0 += w1 * f.x; a1 += w1 * f.y;
        f = __bfloat1622float2(*(const __nv_bfloat162*)&u1.y); a2 += w1 * f.x; a3 += w1 * f.y;
        f = __bfloat1622float2(*(const __nv_bfloat162*)&u2.x); a0 += w2 * f.x; a1 += w2 * f.y;
        f = __bfloat1622float2(*(const __nv_bfloat162*)&u2.y); a2 += w2 * f.x; a3 += w2 * f.y;
        f = __bfloat1622float2(*(const __nv_bfloat162*)&u3.x); a0 += w3 * f.x; a1 += w3 * f.y;
        f = __bfloat1622float2(*(const __nv_bfloat162*)&u3.y); a2 += w3 * f.x; a3 += w3 * f.y;
    }
    for (; j < end; j++) {
        uint2 c = __ldg(g_cw + j);
        uint2 u = hwB[(int)c.x * 32 + lane];
        float w = __uint_as_float(c.y);
        float2 f;
        f = __bfloat1622float2(*(const __nv_bfloat162*)&u.x); a0 += w * f.x; a1 += w * f.y;
        f = __bfloat1622float2(*(const __nv_bfloat162*)&u.y); a2 += w * f.x; a3 += w * f.y;
    }

    a0 = fmaxf(a0, 0.0f);
    a1 = fmaxf(a1, 0.0f);
    a2 = fmaxf(a2, 0.0f);
    a3 = fmaxf(a3, 0.0f);
    if (mode == 0) {
        g_hb[node * 64 + lane * 2 + 0] = __float22bfloat162_rn(make_float2(a0, a1));
        g_hb[node * 64 + lane * 2 + 1] = __float22bfloat162_rn(make_float2(a2, a3));
    } else {
        ((float4*)g_h)[node * 32 + lane] = make_float4(a0, a1, a2, a3);
    }
}

// ---------------- pooling (batch is sorted: run-length local accumulate) ------
__global__ void k_pool(const int* __restrict__ batch) {
    const int CH = 128;
    int base = blockIdx.x * CH;
    int c = threadIdx.x;
    float acc = 0.0f;
    int cur = -1;
    for (int i = 0; i < CH; i++) {
        int node = base + i;
        if (node >= NN) break;
        int g = __ldg(batch + node);
        if (g != cur) {
            if (cur >= 0) atomicAdd(&g_sums[cur * HID + c], acc);
            cur = g; acc = 0.0f;
        }
        acc += g_h[node * HID + c];
    }
    if (cur >= 0) atomicAdd(&g_sums[cur * HID + c], acc);

    if (threadIdx.x == 0) {
        int cur2 = -1; float cnt = 0.0f;
        for (int i = 0; i < CH; i++) {
            int node = base + i;
            if (node >= NN) break;
            int g = __ldg(batch + node);
            if (g != cur2) {
                if (cur2 >= 0) atomicAdd(&g_cnts[cur2], cnt);
                cur2 = g; cnt = 0.0f;
            }
            cnt += 1.0f;
        }
        if (cur2 >= 0) atomicAdd(&g_cnts[cur2], cnt);
    }
}

// ------- heads (fused pooldiv): mu/logvar = (sums/cnt) @ W + b ----------------
__global__ void k_head(const float* __restrict__ Wmu, const float* __restrict__ bmu,
                       const float* __restrict__ Wlv, const float* __restrict__ blv,
                       float* __restrict__ out) {
    int g = blockIdx.x;
    __shared__ float p[HID];
    float inv = 1.0f / fmaxf(g_cnts[g], 1.0f);
    for (int i = threadIdx.x; i < HID; i += blockDim.x) p[i] = g_sums[g * HID + i] * inv;
    __syncthreads();
    int c = threadIdx.x;
    float am = __ldg(bmu + c);
    float al = __ldg(blv + c);
    #pragma unroll 8
    for (int k = 0; k < HID; k++) {
        float pv = p[k];
        am += pv * __ldg(Wmu + k * LAT + c);
        al += pv * __ldg(Wlv + k * LAT + c);
    }
    out[g * LAT + c] = am;
    out[NG * LAT + g * LAT + c] = al;
}

// ---------------- launcher ----------------------------------------------------
extern "C" void kernel_launch(void* const* d_in, const int* in_sizes, int n_in,
                              void* d_out, int out_size) {
    const float* x    = (const float*)d_in[0];
    const int*   ei   = (const int*)d_in[1];   // [2, NE] int32
    const int*   bat  = (const int*)d_in[2];   // [NN] int32
    const float* W1   = (const float*)d_in[3];
    const float* b1   = (const float*)d_in[4];
    const float* W2   = (const float*)d_in[5];
    const float* b2   = (const float*)d_in[6];
    const float* W3   = (const float*)d_in[7];
    const float* b3   = (const float*)d_in[8];
    const float* Wmu  = (const float*)d_in[9];
    const float* bmu  = (const float*)d_in[10];
    const float* Wlv  = (const float*)d_in[11];
    const float* blv  = (const float*)d_in[12];
    float* out = (float*)d_out;

    const int* src = ei;
    const int* dst = ei + NE;

    const int T = 256;
    const int node_blocks = (NN + T - 1) / T;
    const int edge_blocks = (NE + T - 1) / T;
    const int warp8_blocks = (NN + 7) / 8;
    const int tile_blocks = (NN + TN - 1) / TN;

    // ---- CSR build ----
    k_zero_deg<<<node_blocks, T>>>();
    k_count<<<edge_blocks, T>>>(dst);
    k_scan1<<<NBLK, SCAN_B>>>();
    k_scan3<<<NBLK, SCAN_B>>>();
    k_fill<<<edge_blocks, T>>>(src, dst);
    k_convW<<<(NG * HID + T - 1) / T, T>>>(W2, W3);

    // ---- layer 1 (x @ W1 fp32 SIMT -> bf16 hwh) ----
    k_gemm_in_t<<<tile_blocks, T>>>(x, W1);
    k_gather<<<warp8_blocks, T>>>(b1, 0);

    // ---- layer 2 (bf16 HMMA, compensated W) ----
    k_gemm_hid_wmma<<<tile_blocks, T>>>(0);
    k_gather<<<warp8_blocks, T>>>(b2, 0);

    // ---- layer 3 ----
    k_gemm_hid_wmma<<<tile_blocks, T>>>(1);
    k_gather<<<warp8_blocks, T>>>(b3, 1);

    // ---- pooling + heads ----
    k_pool<<<(NN + 127) / 128, HID>>>(bat);
    k_head<<<NG, LAT>>>(Wmu, bmu, Wlv, blv, out);
}